// round 12
// baseline (speedup 1.0000x reference)
#include <cuda_runtime.h>
#include <cstdint>

#define M_TOK   8192
#define D_DIM   4096
#define F_DIM   16384
#define NCHUNK  128
#define F32_EPS 1.1920929e-07f

#define S8_P1 0x01u
#define S8_N1 0xFFu

__device__ __align__(16) uint8_t  g_Xq[(size_t)M_TOK * D_DIM];
__device__ __align__(16) uint8_t  g_Kq[(size_t)F_DIM * D_DIM];
__device__ __align__(16) uint32_t g_Xbits[NCHUNK * M_TOK];
__device__ __align__(16) uint32_t g_Kbits[NCHUNK * F_DIM];
__device__ float g_bx[M_TOK];
__device__ float g_bk[F_DIM];
__device__ float g_bkpart[32][F_DIM];

__device__ __forceinline__ uint32_t smem_u32(const void* p) {
    uint32_t a;
    asm("{ .reg .u64 t; cvta.to.shared.u64 t, %1; cvt.u32.u64 %0, t; }" : "=r"(a) : "l"(p));
    return a;
}
__device__ __forceinline__ uint32_t sw128(uint32_t off) { return off ^ ((off >> 3) & 0x70u); }
__device__ __forceinline__ void cp16(uint32_t dst, const void* src) {
    asm volatile("cp.async.cg.shared.global [%0], [%1], 16;" :: "r"(dst), "l"(src));
}
__device__ __forceinline__ void ldsm4(uint32_t& r0, uint32_t& r1, uint32_t& r2, uint32_t& r3,
                                      uint32_t addr) {
    asm volatile("ldmatrix.sync.aligned.m8n8.x4.shared.b16 {%0,%1,%2,%3}, [%4];"
                 : "=r"(r0), "=r"(r1), "=r"(r2), "=r"(r3) : "r"(addr));
}
__device__ __forceinline__ void ldsm2(uint32_t& r0, uint32_t& r1, uint32_t addr) {
    asm volatile("ldmatrix.sync.aligned.m8n8.x2.shared.b16 {%0,%1}, [%2];"
                 : "=r"(r0), "=r"(r1) : "r"(addr));
}
__device__ __forceinline__ void mma_s8(int* c, uint32_t a0, uint32_t a1, uint32_t a2, uint32_t a3,
                                       uint32_t b0, uint32_t b1) {
    asm volatile("mma.sync.aligned.m16n8k32.row.col.s32.s8.s8.s32 "
                 "{%0,%1,%2,%3}, {%4,%5,%6,%7}, {%8,%9}, {%0,%1,%2,%3};"
                 : "+r"(c[0]), "+r"(c[1]), "+r"(c[2]), "+r"(c[3])
                 : "r"(a0), "r"(a1), "r"(a2), "r"(a3), "r"(b0), "r"(b1));
}
#define CP_COMMIT() asm volatile("cp.async.commit_group;" ::: "memory")
#define BAR_POPC()  asm volatile("bar.sync 1, 384;" ::: "memory")
#define BAR_IMMA()  asm volatile("bar.sync 2, 128;" ::: "memory")

// ---------------------------------------------------------------------------
// Pack passes (validated R6-R11)
// ---------------------------------------------------------------------------
__global__ void pack_x_s8_kernel(const float* __restrict__ x) {
    int token = blockIdx.x * (blockDim.x >> 5) + (threadIdx.x >> 5);
    int lane  = threadIdx.x & 31;
    const float4* row = (const float4*)(x + (size_t)token * D_DIM);
    uint8_t* qrow = g_Xq + (size_t)token * D_DIM;
    const int sh = (lane & 7) * 4;
    float m = 0.f;
    #pragma unroll 4
    for (int c = 0; c < 32; ++c) {
        float4 v = row[c * 32 + lane];
        m = fmaxf(m, fmaxf(fmaxf(fabsf(v.x), fabsf(v.y)), fmaxf(fabsf(v.z), fabsf(v.w))));
        uint32_t b = (v.x < 0.f ? S8_N1 : S8_P1)
                   | ((v.y < 0.f ? S8_N1 : S8_P1) << 8)
                   | ((v.z < 0.f ? S8_N1 : S8_P1) << 16)
                   | ((v.w < 0.f ? S8_N1 : S8_P1) << 24);
        *(uint32_t*)(qrow + c * 128 + lane * 4) = b;
        uint32_t nib = (v.x < 0.f ? 1u : 0u) | (v.y < 0.f ? 2u : 0u)
                     | (v.z < 0.f ? 4u : 0u) | (v.w < 0.f ? 8u : 0u);
        uint32_t w = nib << sh;
        w |= __shfl_xor_sync(0xffffffffu, w, 1);
        w |= __shfl_xor_sync(0xffffffffu, w, 2);
        w |= __shfl_xor_sync(0xffffffffu, w, 4);
        if ((lane & 7) == 0)
            g_Xbits[(c * 4 + (lane >> 3)) * M_TOK + token] = w;
    }
    #pragma unroll
    for (int o = 16; o; o >>= 1) m = fmaxf(m, __shfl_xor_sync(0xffffffffu, m, o));
    if (lane == 0) g_bx[token] = m + F32_EPS;
}

__global__ __launch_bounds__(256)
void pack_k_s8_kernel(const float* __restrict__ kern) {
    __shared__ uint8_t T[128 * 132];
    __shared__ float smax[128];
    const int tid = threadIdx.x;
    const int f0 = blockIdx.x * 128, d0 = blockIdx.y * 128;
    if (tid < 128) smax[tid] = 0.f;
    __syncthreads();

    const int fq = tid & 31;
    float m0 = 0.f, m1 = 0.f, m2 = 0.f, m3 = 0.f;
    #pragma unroll 4
    for (int i = 0; i < 16; ++i) {
        int dr = i * 8 + (tid >> 5);
        float4 v = *(const float4*)(kern + (size_t)(d0 + dr) * F_DIM + f0 + fq * 4);
        m0 = fmaxf(m0, fabsf(v.x)); m1 = fmaxf(m1, fabsf(v.y));
        m2 = fmaxf(m2, fabsf(v.z)); m3 = fmaxf(m3, fabsf(v.w));
        T[(fq * 4 + 0) * 132 + dr] = v.x < 0.f ? S8_N1 : S8_P1;
        T[(fq * 4 + 1) * 132 + dr] = v.y < 0.f ? S8_N1 : S8_P1;
        T[(fq * 4 + 2) * 132 + dr] = v.z < 0.f ? S8_N1 : S8_P1;
        T[(fq * 4 + 3) * 132 + dr] = v.w < 0.f ? S8_N1 : S8_P1;
    }
    atomicMax((int*)&smax[fq * 4 + 0], __float_as_int(m0));
    atomicMax((int*)&smax[fq * 4 + 1], __float_as_int(m1));
    atomicMax((int*)&smax[fq * 4 + 2], __float_as_int(m2));
    atomicMax((int*)&smax[fq * 4 + 3], __float_as_int(m3));
    __syncthreads();

    const int lane = tid & 31;
    const int sh = (lane & 7) * 4;
    const int cbase = (d0 >> 5) + (lane >> 3);
    #pragma unroll 4
    for (int i = 0; i < 16; ++i) {
        int idx = i * 256 + tid;
        int fr = idx >> 5;
        uint32_t w = *(uint32_t*)&T[fr * 132 + lane * 4];
        *(uint32_t*)(g_Kq + (size_t)(f0 + fr) * D_DIM + d0 + lane * 4) = w;
        uint32_t nib = ((w >> 7) & 1u) | ((w >> 14) & 2u)
                     | ((w >> 21) & 4u) | ((w >> 28) & 8u);
        uint32_t bw = nib << sh;
        bw |= __shfl_xor_sync(0xffffffffu, bw, 1);
        bw |= __shfl_xor_sync(0xffffffffu, bw, 2);
        bw |= __shfl_xor_sync(0xffffffffu, bw, 4);
        if ((lane & 7) == 0)
            g_Kbits[(size_t)cbase * F_DIM + f0 + fr] = bw;
    }
    if (tid < 128) g_bkpart[blockIdx.y][f0 + tid] = smax[tid];
}

__global__ void reduce_bk_kernel() {
    int f = blockIdx.x * blockDim.x + threadIdx.x;
    float m = 0.f;
    #pragma unroll
    for (int s = 0; s < 32; ++s) m = fmaxf(m, g_bkpart[s][f]);
    g_bk[f] = m + F32_EPS;
}

// ---------------------------------------------------------------------------
// Decoupled hybrid GEMM, rebalanced 88/40.
//   warps 0-11 (384t): XOR+POPC cols [0,88). 11 compute warps (128x8 tiles),
//                      warp 11 fill-only. 512B k-step, 2 stages, double bar.
//   warps 12-15(128t): s8 mma cols [88,128). 4 warps x (32m x 40n), 5 B-frags
//                      (2x ldsm4 + 1x ldsm2). 128B k-step, 2 stages.
// Smem/CTA: imma 2 x 21504 @0 | popc 2 x 13824 @43008. Total 70656.
//   imma stage: A[128][128] @0 (16KB), B[40][128] @16384 (5120B)
//   popc stage: X 16x512B @0, K 16x352B @8192
// ---------------------------------------------------------------------------
#define STG_I   21504
#define OFF_B   16384
#define POPC_0  43008
#define STG_P   13824
#define SMEM_SZ 70656

__global__ __launch_bounds__(512, 2)
void hybrid_dc_gemm(const float* __restrict__ bias, float* __restrict__ out) {
    extern __shared__ uint8_t smem[];
    const uint32_t sb = smem_u32(smem);
    const int tid = threadIdx.x, wid = tid >> 5, lane = tid & 31;
    const int f0 = blockIdx.x * 128;
    const int t0 = blockIdx.y * 128;

    if (wid < 12) {
        // ============ popcount group: warps 0..11, cols [0,88) ============
        const int pt = tid;                          // 0..383
        auto fillP = [&](int kt, int st) {
            const uint32_t base = sb + POPC_0 + st * STG_P;
            {   // X: 512 cp16 (16 chunks x 32 q)
                int ch = pt >> 5, q = pt & 31;
                cp16(base + ch * 512 + q * 16,
                     g_Xbits + (size_t)(kt * 16 + ch) * M_TOK + t0 + q * 4);
                if (pt < 128) {
                    int ch2 = (pt + 384) >> 5, q2 = (pt + 384) & 31;
                    cp16(base + ch2 * 512 + q2 * 16,
                         g_Xbits + (size_t)(kt * 16 + ch2) * M_TOK + t0 + q2 * 4);
                }
            }
            if (pt < 352) {   // K: 352 cp16 (16 chunks x 22 q of 88 cols)
                int ch = pt / 22, q = pt % 22;
                cp16(base + 8192 + ch * 352 + q * 16,
                     g_Kbits + (size_t)(kt * 16 + ch) * F_DIM + f0 + q * 4);
            }
            CP_COMMIT();
        };

        // 11 compute warps: warp w covers rows 0..127, cols [w*8, w*8+8)
        const int r0 = (lane >> 1) * 8;              // 16 row-groups x 8
        const int c0 = wid * 8 + (lane & 1) * 4;     // 2 col-groups x 4
        int acc[8][4];
        #pragma unroll
        for (int i = 0; i < 8; ++i)
            #pragma unroll
            for (int j = 0; j < 4; ++j) acc[i][j] = 0;

        fillP(0, 0);
        fillP(1, 1);
        for (int kt = 0; kt < 8; ++kt) {
            if (kt < 7) {
                asm volatile("cp.async.wait_group 1;" ::: "memory");
            } else {
                asm volatile("cp.async.wait_group 0;" ::: "memory");
            }
            BAR_POPC();
            if (wid < 11) {
                const uint8_t* base = smem + POPC_0 + (kt & 1) * STG_P;
                #pragma unroll
                for (int c = 0; c < 16; c += 2) {
                    uint32_t xa0[8], kb0[4], xa1[8], kb1[4];
                    *(uint4*)&xa0[0] = *(const uint4*)(base + c * 512 + r0 * 4);
                    *(uint4*)&xa0[4] = *(const uint4*)(base + c * 512 + r0 * 4 + 16);
                    *(uint4*)&kb0[0] = *(const uint4*)(base + 8192 + c * 352 + c0 * 4);
                    *(uint4*)&xa1[0] = *(const uint4*)(base + (c + 1) * 512 + r0 * 4);
                    *(uint4*)&xa1[4] = *(const uint4*)(base + (c + 1) * 512 + r0 * 4 + 16);
                    *(uint4*)&kb1[0] = *(const uint4*)(base + 8192 + (c + 1) * 352 + c0 * 4);
                    #pragma unroll
                    for (int i = 0; i < 8; ++i)
                        #pragma unroll
                        for (int j = 0; j < 4; ++j)
                            acc[i][j] += __popc(xa0[i] ^ kb0[j]) + __popc(xa1[i] ^ kb1[j]);
                }
            }
            BAR_POPC();                              // all reads of this stage done
            if (kt + 2 < 8) fillP(kt + 2, (kt + 2) & 1);
        }

        if (wid < 11) {
            const int trow = t0 + r0, tcol = f0 + c0;
            float bk4[4], bs4[4];
            #pragma unroll
            for (int j = 0; j < 4; ++j) { bk4[j] = g_bk[tcol + j]; bs4[j] = bias[tcol + j]; }
            #pragma unroll
            for (int i = 0; i < 8; ++i) {
                float sx = 0.25f * g_bx[trow + i];
                float4 r;
                r.x = fmaf(sx * bk4[0], (float)(D_DIM - 2 * acc[i][0]), bs4[0]);
                r.y = fmaf(sx * bk4[1], (float)(D_DIM - 2 * acc[i][1]), bs4[1]);
                r.z = fmaf(sx * bk4[2], (float)(D_DIM - 2 * acc[i][2]), bs4[2]);
                r.w = fmaf(sx * bk4[3], (float)(D_DIM - 2 * acc[i][3]), bs4[3]);
                *(float4*)(out + (size_t)(trow + i) * F_DIM + tcol) = r;
            }
        }
    } else {
        // ============ imma group: warps 12..15, cols [88,128) ============
        const int t = tid - 384;                     // 0..127
        const int iw = wid - 12;                     // 0..3 (m-slice)
        const uint8_t* __restrict__ gA  = g_Xq + (size_t)t0 * D_DIM;
        const uint8_t* __restrict__ gBq = g_Kq + (size_t)(f0 + 88) * D_DIM;  // 40 rows

        auto fillI = [&](int kt, int st) {
            const uint32_t base = sb + st * STG_I;
            const size_t gk = (size_t)kt * 128;
            #pragma unroll
            for (int i = 0; i < 8; ++i) {
                int idx = i * 128 + t;               // 0..1023
                int r = idx >> 3, c = (idx & 7) << 4;
                cp16(base + sw128(r * 128 + c), gA + (size_t)r * D_DIM + gk + c);
            }
            #pragma unroll
            for (int i = 0; i < 3; ++i) {
                int idx = i * 128 + t;               // 0..383, valid < 320
                if (idx < 320) {
                    int r = idx >> 3, c = (idx & 7) << 4;
                    cp16(base + OFF_B + sw128(r * 128 + c),
                         gBq + (size_t)r * D_DIM + gk + c);
                }
            }
            CP_COMMIT();
        };

        int acc[2][5][4];
        #pragma unroll
        for (int mi = 0; mi < 2; ++mi)
            #pragma unroll
            for (int ni = 0; ni < 5; ++ni)
                #pragma unroll
                for (int r = 0; r < 4; ++r) acc[mi][ni][r] = 0;

        const int l15 = lane & 15;
        const int khalf = (lane & 16);
        const int arow = iw * 32 + l15;
        // frag-4 ldsm2 address pieces (lanes 0..15 meaningful)
        const int b2row = 32 + (lane & 7);
        const int b2kh  = ((lane >> 3) & 1) * 16;

        fillI(0, 0);
        for (int kt = 0; kt < 32; ++kt) {
            if (kt < 31) {
                fillI(kt + 1, (kt + 1) & 1);
                asm volatile("cp.async.wait_group 1;" ::: "memory");
            } else {
                asm volatile("cp.async.wait_group 0;" ::: "memory");
            }
            BAR_IMMA();
            const uint32_t stb = sb + (kt & 1) * STG_I;
            const uint32_t bSt = stb + OFF_B;
            #pragma unroll
            for (int ks = 0; ks < 4; ++ks) {
                const int kcol = ks * 32 + khalf;
                uint32_t b0, b1, b2, b3, b4, b5, b6, b7, b8, b9;
                ldsm4(b0, b1, b2, b3, bSt + sw128(l15 * 128 + kcol));        // frags 0,1
                ldsm4(b4, b5, b6, b7, bSt + sw128((16 + l15) * 128 + kcol)); // frags 2,3
                ldsm2(b8, b9, bSt + sw128(b2row * 128 + ks * 32 + b2kh));    // frag 4
                #pragma unroll
                for (int mi = 0; mi < 2; ++mi) {
                    uint32_t a0, a1, a2, a3;
                    ldsm4(a0, a1, a2, a3, stb + sw128((arow + mi * 16) * 128 + kcol));
                    mma_s8(acc[mi][0], a0, a1, a2, a3, b0, b2);
                    mma_s8(acc[mi][1], a0, a1, a2, a3, b1, b3);
                    mma_s8(acc[mi][2], a0, a1, a2, a3, b4, b6);
                    mma_s8(acc[mi][3], a0, a1, a2, a3, b5, b7);
                    mma_s8(acc[mi][4], a0, a1, a2, a3, b8, b9);
                }
            }
            BAR_IMMA();
        }

        const int lrow = lane >> 2;
        const int lcol = (lane & 3) * 2;
        const int rbase = t0 + iw * 32;
        const int cbase = f0 + 88;
        #pragma unroll
        for (int mi = 0; mi < 2; ++mi) {
            float sx0 = 0.25f * g_bx[rbase + mi * 16 + lrow];
            float sx1 = 0.25f * g_bx[rbase + mi * 16 + lrow + 8];
            #pragma unroll
            for (int ni = 0; ni < 5; ++ni) {
                int c = cbase + ni * 8 + lcol;
                float k0v = g_bk[c], k1v = g_bk[c + 1];
                float b0v = bias[c], b1v = bias[c + 1];
                float2 v0, v1;
                v0.x = fmaf(sx0 * k0v, (float)acc[mi][ni][0], b0v);
                v0.y = fmaf(sx0 * k1v, (float)acc[mi][ni][1], b1v);
                v1.x = fmaf(sx1 * k0v, (float)acc[mi][ni][2], b0v);
                v1.y = fmaf(sx1 * k1v, (float)acc[mi][ni][3], b1v);
                *(float2*)(out + (size_t)(rbase + mi * 16 + lrow) * F_DIM + c) = v0;
                *(float2*)(out + (size_t)(rbase + mi * 16 + lrow + 8) * F_DIM + c) = v1;
            }
        }
    }
}

// ---------------------------------------------------------------------------
extern "C" void kernel_launch(void* const* d_in, const int* in_sizes, int n_in,
                              void* d_out, int out_size) {
    const float* x    = (const float*)d_in[0];
    const float* kern = (const float*)d_in[1];
    const float* bias = (const float*)d_in[2];
    float* out = (float*)d_out;

    pack_x_s8_kernel<<<M_TOK / 8, 256>>>(x);
    dim3 gk(F_DIM / 128, D_DIM / 128);
    pack_k_s8_kernel<<<gk, 256>>>(kern);
    reduce_bk_kernel<<<F_DIM / 256, 256>>>();

    cudaFuncSetAttribute(hybrid_dc_gemm,
                         cudaFuncAttributeMaxDynamicSharedMemorySize, SMEM_SZ);
    dim3 gg(F_DIM / 128, M_TOK / 128);
    hybrid_dc_gemm<<<gg, 512, SMEM_SZ>>>(bias, out);
}

// round 14
// speedup vs baseline: 1.0526x; 1.0526x over previous
#include <cuda_runtime.h>
#include <cstdint>

#define M_TOK   8192
#define D_DIM   4096
#define F_DIM   16384
#define NCHUNK  128
#define F32_EPS 1.1920929e-07f

#define S8_P1 0x01u
#define S8_N1 0xFFu

__device__ __align__(16) uint8_t  g_Xq[(size_t)M_TOK * D_DIM];
__device__ __align__(16) uint8_t  g_Kq[(size_t)F_DIM * D_DIM];
__device__ __align__(16) uint32_t g_Xbits[NCHUNK * M_TOK];
__device__ __align__(16) uint32_t g_Kbits[NCHUNK * F_DIM];
__device__ float g_bx[M_TOK];
__device__ float g_bk[F_DIM];
__device__ float g_bkpart[32][F_DIM];

__device__ __forceinline__ uint32_t smem_u32(const void* p) {
    uint32_t a;
    asm("{ .reg .u64 t; cvta.to.shared.u64 t, %1; cvt.u32.u64 %0, t; }" : "=r"(a) : "l"(p));
    return a;
}
__device__ __forceinline__ uint32_t sw128(uint32_t off) { return off ^ ((off >> 3) & 0x70u); }
__device__ __forceinline__ void cp16(uint32_t dst, const void* src) {
    asm volatile("cp.async.cg.shared.global [%0], [%1], 16;" :: "r"(dst), "l"(src));
}
__device__ __forceinline__ void ldsm4(uint32_t& r0, uint32_t& r1, uint32_t& r2, uint32_t& r3,
                                      uint32_t addr) {
    asm volatile("ldmatrix.sync.aligned.m8n8.x4.shared.b16 {%0,%1,%2,%3}, [%4];"
                 : "=r"(r0), "=r"(r1), "=r"(r2), "=r"(r3) : "r"(addr));
}
__device__ __forceinline__ void mma_s8(int* c, uint32_t a0, uint32_t a1, uint32_t a2, uint32_t a3,
                                       uint32_t b0, uint32_t b1) {
    asm volatile("mma.sync.aligned.m16n8k32.row.col.s32.s8.s8.s32 "
                 "{%0,%1,%2,%3}, {%4,%5,%6,%7}, {%8,%9}, {%0,%1,%2,%3};"
                 : "+r"(c[0]), "+r"(c[1]), "+r"(c[2]), "+r"(c[3])
                 : "r"(a0), "r"(a1), "r"(a2), "r"(a3), "r"(b0), "r"(b1));
}
#define CP_COMMIT() asm volatile("cp.async.commit_group;" ::: "memory")
#define BAR_POPC()  asm volatile("bar.sync 1, 384;" ::: "memory")
#define BAR_IMMA()  asm volatile("bar.sync 2, 128;" ::: "memory")

// ---------------------------------------------------------------------------
// Pack passes (validated R6-R11)
// ---------------------------------------------------------------------------
__global__ void pack_x_s8_kernel(const float* __restrict__ x) {
    int token = blockIdx.x * (blockDim.x >> 5) + (threadIdx.x >> 5);
    int lane  = threadIdx.x & 31;
    const float4* row = (const float4*)(x + (size_t)token * D_DIM);
    uint8_t* qrow = g_Xq + (size_t)token * D_DIM;
    const int sh = (lane & 7) * 4;
    float m = 0.f;
    #pragma unroll 4
    for (int c = 0; c < 32; ++c) {
        float4 v = row[c * 32 + lane];
        m = fmaxf(m, fmaxf(fmaxf(fabsf(v.x), fabsf(v.y)), fmaxf(fabsf(v.z), fabsf(v.w))));
        uint32_t b = (v.x < 0.f ? S8_N1 : S8_P1)
                   | ((v.y < 0.f ? S8_N1 : S8_P1) << 8)
                   | ((v.z < 0.f ? S8_N1 : S8_P1) << 16)
                   | ((v.w < 0.f ? S8_N1 : S8_P1) << 24);
        *(uint32_t*)(qrow + c * 128 + lane * 4) = b;
        uint32_t nib = (v.x < 0.f ? 1u : 0u) | (v.y < 0.f ? 2u : 0u)
                     | (v.z < 0.f ? 4u : 0u) | (v.w < 0.f ? 8u : 0u);
        uint32_t w = nib << sh;
        w |= __shfl_xor_sync(0xffffffffu, w, 1);
        w |= __shfl_xor_sync(0xffffffffu, w, 2);
        w |= __shfl_xor_sync(0xffffffffu, w, 4);
        if ((lane & 7) == 0)
            g_Xbits[(c * 4 + (lane >> 3)) * M_TOK + token] = w;
    }
    #pragma unroll
    for (int o = 16; o; o >>= 1) m = fmaxf(m, __shfl_xor_sync(0xffffffffu, m, o));
    if (lane == 0) g_bx[token] = m + F32_EPS;
}

__global__ __launch_bounds__(256)
void pack_k_s8_kernel(const float* __restrict__ kern) {
    __shared__ uint8_t T[128 * 132];
    __shared__ float smax[128];
    const int tid = threadIdx.x;
    const int f0 = blockIdx.x * 128, d0 = blockIdx.y * 128;
    if (tid < 128) smax[tid] = 0.f;
    __syncthreads();

    const int fq = tid & 31;
    float m0 = 0.f, m1 = 0.f, m2 = 0.f, m3 = 0.f;
    #pragma unroll 4
    for (int i = 0; i < 16; ++i) {
        int dr = i * 8 + (tid >> 5);
        float4 v = *(const float4*)(kern + (size_t)(d0 + dr) * F_DIM + f0 + fq * 4);
        m0 = fmaxf(m0, fabsf(v.x)); m1 = fmaxf(m1, fabsf(v.y));
        m2 = fmaxf(m2, fabsf(v.z)); m3 = fmaxf(m3, fabsf(v.w));
        T[(fq * 4 + 0) * 132 + dr] = v.x < 0.f ? S8_N1 : S8_P1;
        T[(fq * 4 + 1) * 132 + dr] = v.y < 0.f ? S8_N1 : S8_P1;
        T[(fq * 4 + 2) * 132 + dr] = v.z < 0.f ? S8_N1 : S8_P1;
        T[(fq * 4 + 3) * 132 + dr] = v.w < 0.f ? S8_N1 : S8_P1;
    }
    atomicMax((int*)&smax[fq * 4 + 0], __float_as_int(m0));
    atomicMax((int*)&smax[fq * 4 + 1], __float_as_int(m1));
    atomicMax((int*)&smax[fq * 4 + 2], __float_as_int(m2));
    atomicMax((int*)&smax[fq * 4 + 3], __float_as_int(m3));
    __syncthreads();

    const int lane = tid & 31;
    const int sh = (lane & 7) * 4;
    const int cbase = (d0 >> 5) + (lane >> 3);
    #pragma unroll 4
    for (int i = 0; i < 16; ++i) {
        int idx = i * 256 + tid;
        int fr = idx >> 5;
        uint32_t w = *(uint32_t*)&T[fr * 132 + lane * 4];
        *(uint32_t*)(g_Kq + (size_t)(f0 + fr) * D_DIM + d0 + lane * 4) = w;
        uint32_t nib = ((w >> 7) & 1u) | ((w >> 14) & 2u)
                     | ((w >> 21) & 4u) | ((w >> 28) & 8u);
        uint32_t bw = nib << sh;
        bw |= __shfl_xor_sync(0xffffffffu, bw, 1);
        bw |= __shfl_xor_sync(0xffffffffu, bw, 2);
        bw |= __shfl_xor_sync(0xffffffffu, bw, 4);
        if ((lane & 7) == 0)
            g_Kbits[(size_t)cbase * F_DIM + f0 + fr] = bw;
    }
    if (tid < 128) g_bkpart[blockIdx.y][f0 + tid] = smax[tid];
}

__global__ void reduce_bk_kernel() {
    int f = blockIdx.x * blockDim.x + threadIdx.x;
    float m = 0.f;
    #pragma unroll
    for (int s = 0; s < 32; ++s) m = fmaxf(m, g_bkpart[s][f]);
    g_bk[f] = m + F32_EPS;
}

// ---------------------------------------------------------------------------
// Decoupled hybrid GEMM (R11 structure, 96/32) + CSA popcount compression.
//   warps 0-11 (384t): XOR + CSA(3:2) + POPC, cols [0,96), 512B k-step,
//                      2 stages, double barrier (race-free)
//   warps 12-15(128t): s8 mma cols [96,128), 256B k-step, 2 stages
// Smem: imma 2 x 40960 @0; popc 2 x 14336 @81920. Total 110592.
// popc stage: X 16x512B @0 | K 16x384B @8192
// ---------------------------------------------------------------------------
#define STG_I   40960
#define OFF_B   32768
#define POPC_0  81920
#define STG_P   14336
#define SMEM_SZ 110592

__global__ __launch_bounds__(512, 2)
void hybrid_dc_gemm(const float* __restrict__ bias, float* __restrict__ out) {
    extern __shared__ uint8_t smem[];
    const uint32_t sb = smem_u32(smem);
    const int tid = threadIdx.x, wid = tid >> 5, lane = tid & 31;
    const int f0 = blockIdx.x * 128;
    const int t0 = blockIdx.y * 128;

    if (wid < 12) {
        // ============ popcount group: warps 0..11, cols [0,96) ============
        const int pt = tid;                          // 0..383
        auto fillP = [&](int kt, int st) {
            const uint32_t base = sb + POPC_0 + st * STG_P;
            {   // X: 512 cp16
                int ch = pt >> 5, q = pt & 31;
                cp16(base + ch * 512 + q * 16,
                     g_Xbits + (size_t)(kt * 16 + ch) * M_TOK + t0 + q * 4);
                if (pt < 128) {
                    int ch2 = (pt + 384) >> 5, q2 = (pt + 384) & 31;
                    cp16(base + ch2 * 512 + q2 * 16,
                         g_Xbits + (size_t)(kt * 16 + ch2) * M_TOK + t0 + q2 * 4);
                }
            }
            {   // K: 384 cp16
                int ch = pt / 24, q = pt % 24;
                cp16(base + 8192 + ch * 384 + q * 16,
                     g_Kbits + (size_t)(kt * 16 + ch) * F_DIM + f0 + q * 4);
            }
            CP_COMMIT();
        };

        const int pm = wid & 3, pn = wid >> 2;       // 4m x 3n warp grid
        const int r0 = pm * 32 + (lane >> 3) * 8;
        const int c0 = pn * 32 + (lane & 7) * 4;
        int acc[8][4];
        #pragma unroll
        for (int i = 0; i < 8; ++i)
            #pragma unroll
            for (int j = 0; j < 4; ++j) acc[i][j] = 0;

        fillP(0, 0);
        fillP(1, 1);
        for (int kt = 0; kt < 8; ++kt) {
            if (kt < 7) {
                asm volatile("cp.async.wait_group 1;" ::: "memory");
            } else {
                asm volatile("cp.async.wait_group 0;" ::: "memory");
            }
            BAR_POPC();
            const uint8_t* base = smem + POPC_0 + (kt & 1) * STG_P;

            // 16 chunks = 5 CSA triples + 1 plain chunk.
            #pragma unroll
            for (int tr = 0; tr < 5; ++tr) {
                const int c = tr * 3;
                uint32_t kb0[4], kb1[4], kb2[4];
                *(uint4*)&kb0[0] = *(const uint4*)(base + 8192 + c * 384 + c0 * 4);
                *(uint4*)&kb1[0] = *(const uint4*)(base + 8192 + (c + 1) * 384 + c0 * 4);
                *(uint4*)&kb2[0] = *(const uint4*)(base + 8192 + (c + 2) * 384 + c0 * 4);
                #pragma unroll
                for (int h = 0; h < 2; ++h) {
                    uint32_t xa0[4], xa1[4], xa2[4];
                    *(uint4*)&xa0[0] = *(const uint4*)(base + c * 512 + r0 * 4 + h * 16);
                    *(uint4*)&xa1[0] = *(const uint4*)(base + (c + 1) * 512 + r0 * 4 + h * 16);
                    *(uint4*)&xa2[0] = *(const uint4*)(base + (c + 2) * 512 + r0 * 4 + h * 16);
                    #pragma unroll
                    for (int i = 0; i < 4; ++i)
                        #pragma unroll
                        for (int j = 0; j < 4; ++j) {
                            uint32_t e0 = xa0[i] ^ kb0[j];
                            uint32_t e1 = xa1[i] ^ kb1[j];
                            uint32_t e2 = xa2[i] ^ kb2[j];
                            uint32_t s  = e0 ^ e1 ^ e2;                    // LOP3 0x96
                            uint32_t mj = (e0 & e1) | (e2 & (e0 | e1));    // LOP3 0xE8
                            acc[h * 4 + i][j] += __popc(s) + 2 * __popc(mj);
                        }
                }
            }
            {   // leftover chunk 15
                uint32_t kb[4], xa[8];
                *(uint4*)&kb[0] = *(const uint4*)(base + 8192 + 15 * 384 + c0 * 4);
                *(uint4*)&xa[0] = *(const uint4*)(base + 15 * 512 + r0 * 4);
                *(uint4*)&xa[4] = *(const uint4*)(base + 15 * 512 + r0 * 4 + 16);
                #pragma unroll
                for (int i = 0; i < 8; ++i)
                    #pragma unroll
                    for (int j = 0; j < 4; ++j)
                        acc[i][j] += __popc(xa[i] ^ kb[j]);
            }
            BAR_POPC();                              // reads of this stage done
            if (kt + 2 < 8) fillP(kt + 2, (kt + 2) & 1);
        }

        const int trow = t0 + r0, tcol = f0 + c0;
        float bk4[4], bs4[4];
        #pragma unroll
        for (int j = 0; j < 4; ++j) { bk4[j] = g_bk[tcol + j]; bs4[j] = bias[tcol + j]; }
        #pragma unroll
        for (int i = 0; i < 8; ++i) {
            float sx = 0.25f * g_bx[trow + i];
            float4 r;
            r.x = fmaf(sx * bk4[0], (float)(D_DIM - 2 * acc[i][0]), bs4[0]);
            r.y = fmaf(sx * bk4[1], (float)(D_DIM - 2 * acc[i][1]), bs4[1]);
            r.z = fmaf(sx * bk4[2], (float)(D_DIM - 2 * acc[i][2]), bs4[2]);
            r.w = fmaf(sx * bk4[3], (float)(D_DIM - 2 * acc[i][3]), bs4[3]);
            *(float4*)(out + (size_t)(trow + i) * F_DIM + tcol) = r;
        }
    } else {
        // ============ imma group: warps 12..15, cols [96,128) ============
        const int t = tid - 384;                     // 0..127
        const uint8_t* __restrict__ gA  = g_Xq + (size_t)t0 * D_DIM;
        const uint8_t* __restrict__ gBq = g_Kq + (size_t)(f0 + 96) * D_DIM;

        auto fillI = [&](int kt, int st) {
            const uint32_t base = sb + st * STG_I;
            const size_t gk = (size_t)kt * 256;
            #pragma unroll
            for (int i = 0; i < 16; ++i) {
                int idx = i * 128 + t;
                int sub = idx >> 10, r = (idx >> 3) & 127, c = (idx & 7) << 4;
                cp16(base + sub * 16384 + sw128(r * 128 + c),
                     gA + (size_t)r * D_DIM + gk + sub * 128 + c);
            }
            #pragma unroll
            for (int i = 0; i < 4; ++i) {
                int idx = i * 128 + t;
                int sub = idx >> 8, r = (idx >> 3) & 31, c = (idx & 7) << 4;
                cp16(base + OFF_B + sub * 4096 + sw128(r * 128 + c),
                     gBq + (size_t)r * D_DIM + gk + sub * 128 + c);
            }
            CP_COMMIT();
        };

        const int iw = wid - 12;
        const int wm = iw & 1, wn = iw >> 1;         // 2m x 2n, warp tile 64x16
        int acc[4][2][4];
        #pragma unroll
        for (int mi = 0; mi < 4; ++mi)
            #pragma unroll
            for (int ni = 0; ni < 2; ++ni)
                #pragma unroll
                for (int r = 0; r < 4; ++r) acc[mi][ni][r] = 0;

        const int arow = wm * 64 + (lane & 15);
        const int brow = wn * 16 + (lane & 15);
        const int khalf = (lane & 16);

        fillI(0, 0);
        for (int kt = 0; kt < 16; ++kt) {
            if (kt < 15) {
                fillI(kt + 1, (kt + 1) & 1);
                asm volatile("cp.async.wait_group 1;" ::: "memory");
            } else {
                asm volatile("cp.async.wait_group 0;" ::: "memory");
            }
            BAR_IMMA();
            const uint32_t stb = sb + (kt & 1) * STG_I;
            #pragma unroll
            for (int ks = 0; ks < 8; ++ks) {
                const int sub = ks >> 2;
                const int kcol = (ks & 3) * 32 + khalf;
                const uint32_t aSt = stb + sub * 16384;
                const uint32_t bSt = stb + OFF_B + sub * 4096;
                uint32_t b0, b1, b2, b3;
                ldsm4(b0, b1, b2, b3, bSt + sw128(brow * 128 + kcol));
                #pragma unroll
                for (int mi = 0; mi < 4; ++mi) {
                    uint32_t a0, a1, a2, a3;
                    ldsm4(a0, a1, a2, a3, aSt + sw128((arow + mi * 16) * 128 + kcol));
                    mma_s8(acc[mi][0], a0, a1, a2, a3, b0, b2);
                    mma_s8(acc[mi][1], a0, a1, a2, a3, b1, b3);
                }
            }
            BAR_IMMA();
        }

        const int lrow = lane >> 2;
        const int lcol = (lane & 3) * 2;
        const int rbase = t0 + wm * 64;
        const int cbase = f0 + 96 + wn * 16;
        #pragma unroll
        for (int mi = 0; mi < 4; ++mi) {
            float sx0 = 0.25f * g_bx[rbase + mi * 16 + lrow];
            float sx1 = 0.25f * g_bx[rbase + mi * 16 + lrow + 8];
            #pragma unroll
            for (int ni = 0; ni < 2; ++ni) {
                int c = cbase + ni * 8 + lcol;
                float k0v = g_bk[c], k1v = g_bk[c + 1];
                float b0v = bias[c], b1v = bias[c + 1];
                float2 v0, v1;
                v0.x = fmaf(sx0 * k0v, (float)acc[mi][ni][0], b0v);
                v0.y = fmaf(sx0 * k1v, (float)acc[mi][ni][1], b1v);
                v1.x = fmaf(sx1 * k0v, (float)acc[mi][ni][2], b0v);
                v1.y = fmaf(sx1 * k1v, (float)acc[mi][ni][3], b1v);
                *(float2*)(out + (size_t)(rbase + mi * 16 + lrow) * F_DIM + c) = v0;
                *(float2*)(out + (size_t)(rbase + mi * 16 + lrow + 8) * F_DIM + c) = v1;
            }
        }
    }
}

// ---------------------------------------------------------------------------
extern "C" void kernel_launch(void* const* d_in, const int* in_sizes, int n_in,
                              void* d_out, int out_size) {
    const float* x    = (const float*)d_in[0];
    const float* kern = (const float*)d_in[1];
    const float* bias = (const float*)d_in[2];
    float* out = (float*)d_out;

    pack_x_s8_kernel<<<M_TOK / 8, 256>>>(x);
    dim3 gk(F_DIM / 128, D_DIM / 128);
    pack_k_s8_kernel<<<gk, 256>>>(kern);
    reduce_bk_kernel<<<F_DIM / 256, 256>>>();

    cudaFuncSetAttribute(hybrid_dc_gemm,
                         cudaFuncAttributeMaxDynamicSharedMemorySize, SMEM_SZ);
    dim3 gg(F_DIM / 128, M_TOK / 128);
    hybrid_dc_gemm<<<gg, 512, SMEM_SZ>>>(bias, out);
}